// round 11
// baseline (speedup 1.0000x reference)
#include <cuda_runtime.h>

#define B_ 64
#define R_ 32
#define N_ 16384
#define D_ 64
#define O_ 8
#define SPLIT_ 8
#define CHUNK_ (N_ / SPLIT_)    /* 2048 = 256 threads * 8 n */
#define THREADS_ 256
#define NWARP_ (THREADS_ / 32)
#define BATCH_ 8

// Plain-store partials: every slot written every launch -> no zeroing pass.
__device__ __align__(16) float g_part[B_][SPLIT_][D_];
__device__ float g_cnt[B_][SPLIT_];
// Completion counters (zero-init .bss; finalizer resets them each launch).
__device__ unsigned g_done[B_];

// ---------------------------------------------------------------------------
// Single launch, single wave. grid = (B, 8) = 512 blocks, block = 256.
// Thread owns 8 consecutive n (warp = 256 contiguous mask bytes, coalesced).
// o_types int4 loaded only for 4-n groups with a mask hit (independent loads
// for the two groups -> concurrent). Hits gathered warp-cooperatively in
// BATCHES of up to 8: all row loads issued first (one memory round), then
// the butterfly reductions run as interleaved independent shfl chains.
// Last block per b finalizes its 32 outputs.
// ---------------------------------------------------------------------------
__global__ __launch_bounds__(THREADS_)
void ssfw_fused(const float* __restrict__ l_local,
                const float* __restrict__ hctx,
                const float* __restrict__ lambda_so,
                const int*   __restrict__ center_o,
                const int*   __restrict__ o_types,
                const void*  __restrict__ adj,
                const void*  __restrict__ two,
                float*       __restrict__ out) {
    const int b    = blockIdx.x;
    const int part = blockIdx.y;
    const int tid  = threadIdx.x;
    const int warp = tid >> 5;
    const int lane = tid & 31;

    __shared__ __align__(16) float s_part[NWARP_][D_];
    __shared__ int  sh_bytes;       // 1 if masks are packed bytes (numpy bool)
    __shared__ int  s_cnt;
    __shared__ int  s_last;
    if (tid == 0) { sh_bytes = 0; s_cnt = 0; }

    // ---- round-1 loads issued up front (independent; high MLP) ----
    // probe: first 1KB of each mask array (identical across blocks, L2-hot)
    unsigned pa0 = ((const unsigned*)adj)[tid];
    unsigned pt0 = ((const unsigned*)two)[tid];

    const int n_glob = b * N_ + part * CHUNK_ + tid * 8;   // fits in int (max 1M)

    // speculative byte-view mask loads: 8 bytes per array (8B-aligned)
    uint2 a2 = *(const uint2*)((const unsigned char*)adj + n_glob);
    uint2 t2 = *(const uint2*)((const unsigned char*)two + n_glob);
    const int ctr = center_o[b];

    // classify: any probe word outside {0, 1, 0x3F800000} => packed bytes
    {
        int isb = 0;
        if (pa0 != 0u && pa0 != 1u && pa0 != 0x3F800000u) isb = 1;
        if (pt0 != 0u && pt0 != 1u && pt0 != 0x3F800000u) isb = 1;
        if (isb) atomicOr(&sh_bytes, 1);
    }
    __syncthreads();

    // hit bytes per 4-n group: u0 covers n_glob..+3, u1 covers +4..+7
    unsigned u0, u1;
    if (sh_bytes) {
        u0 = a2.x | t2.x;
        u1 = a2.y | t2.y;
    } else {
        // word masks: nonzero == true for BOTH int32 0/1 and f32 0.0/1.0
        const uint4* wa = (const uint4*)((const int*)adj + n_glob);
        const uint4* wt = (const uint4*)((const int*)two + n_glob);
        uint4 a0 = wa[0], a1 = wa[1], b0 = wt[0], b1 = wt[1];
        u0 = ((a0.x | b0.x) ? 1u : 0u)       | ((a0.y | b0.y) ? 0x100u : 0u)
           | ((a0.z | b0.z) ? 0x10000u : 0u) | ((a0.w | b0.w) ? 0x1000000u : 0u);
        u1 = ((a1.x | b1.x) ? 1u : 0u)       | ((a1.y | b1.y) ? 0x100u : 0u)
           | ((a1.z | b1.z) ? 0x10000u : 0u) | ((a1.w | b1.w) ? 0x1000000u : 0u);
    }

    // o_types loaded only for hit groups; the two loads are independent
    int hb = 0;
    if (u0) {
        const int4 ov = *(const int4*)(o_types + n_glob);
        if ((u0 & 0xffu)       && ov.x == ctr) hb |= 1;
        if ((u0 & 0xff00u)     && ov.y == ctr) hb |= 2;
        if ((u0 & 0xff0000u)   && ov.z == ctr) hb |= 4;
        if ((u0 & 0xff000000u) && ov.w == ctr) hb |= 8;
    }
    if (u1) {
        const int4 ov = *(const int4*)(o_types + n_glob + 4);
        if ((u1 & 0xffu)       && ov.x == ctr) hb |= 16;
        if ((u1 & 0xff00u)     && ov.y == ctr) hb |= 32;
        if ((u1 & 0xff0000u)   && ov.z == ctr) hb |= 64;
        if ((u1 & 0xff000000u) && ov.w == ctr) hb |= 128;
    }

    // ---- warp-cooperative BATCHED gather; lane owns dims {2L, 2L+1} ----
    float accx = 0.0f, accy = 0.0f;
    int   wcnt = 0;
    unsigned hitmask = __ballot_sync(0xffffffffu, hb != 0);   // uniform
    while (hitmask) {
        // fill a batch of up to BATCH_ row indices (uniform across the warp)
        int idx[BATCH_];
        int nb = 0;
        while (hitmask) {
            int src = __ffs(hitmask) - 1;
            int shb = __shfl_sync(0xffffffffu, hb, src);
            if (nb + __popc(shb) > BATCH_) break;
            int snb = __shfl_sync(0xffffffffu, n_glob, src);
            while (shb) {
                int j = __ffs(shb) - 1;
                shb &= shb - 1;
                idx[nb++] = snb + j;
            }
            hitmask &= hitmask - 1;
        }
        // issue all row loads (independent -> single memory round)
        float2 v[BATCH_];
        #pragma unroll
        for (int h = 0; h < BATCH_; h++)
            if (h < nb)
                v[h] = ((const float2*)(hctx + (long long)idx[h] * D_))[lane];
        // interleaved butterfly reductions (independent shfl chains)
        float sq[BATCH_];
        #pragma unroll
        for (int h = 0; h < BATCH_; h++)
            if (h < nb) sq[h] = v[h].x * v[h].x + v[h].y * v[h].y;
        #pragma unroll
        for (int o = 16; o > 0; o >>= 1) {
            #pragma unroll
            for (int h = 0; h < BATCH_; h++)
                if (h < nb) sq[h] += __shfl_xor_sync(0xffffffffu, sq[h], o);
        }
        #pragma unroll
        for (int h = 0; h < BATCH_; h++) {
            if (h < nb) {
                float rn = rsqrtf(fmaxf(sq[h], 1e-12f));
                accx += v[h].x * rn;
                accy += v[h].y * rn;
            }
        }
        wcnt += nb;
    }
    s_part[warp][lane * 2]     = accx;
    s_part[warp][lane * 2 + 1] = accy;
    if (lane == 0 && wcnt) atomicAdd(&s_cnt, wcnt);
    __syncthreads();

    // ---- reduce 8 warp slices, publish partials ----
    if (tid < D_) {
        float acc = 0.0f;
        #pragma unroll
        for (int w = 0; w < NWARP_; w++) acc += s_part[w][tid];
        g_part[b][part][tid] = acc;
    }
    if (tid == 0) g_cnt[b][part] = (float)s_cnt;

    // ---- last-block-done detection ----
    if (tid == 0) {
        __threadfence();
        unsigned old = atomicAdd(&g_done[b], 1u);
        s_last = (old == SPLIT_ - 1);
    }
    __syncthreads();
    if (!s_last) return;

    // ---- finalize b (this block only) ----
    __shared__ __align__(16) float s_sum[D_];
    __shared__ float s_nv;
    if (tid < D_) {
        float acc = 0.0f;
        #pragma unroll
        for (int p = 0; p < SPLIT_; p++) acc += g_part[b][p][tid];
        s_sum[tid] = acc;
    }
    if (tid == 0) {
        float nv = 0.0f;
        #pragma unroll
        for (int p = 0; p < SPLIT_; p++) nv += g_cnt[b][p];
        s_nv = nv;
        g_done[b] = 0;                  // reset for next graph replay
    }
    __syncthreads();

    const float  nv = s_nv;
    const float2 sv = *(const float2*)(&s_sum[lane * 2]);

    #pragma unroll
    for (int rr = 0; rr < 4; rr++) {    // warp w handles r = w, w+8, w+16, w+24
        const int r = warp + rr * 8;
        const float2* lrow = (const float2*)(l_local + ((long long)b * R_ + r) * D_);
        float2 lv = lrow[lane];

        float sq = lv.x * lv.x + lv.y * lv.y;
        float dp = lv.x * sv.x + lv.y * sv.y;
        #pragma unroll
        for (int o = 16; o > 0; o >>= 1) {
            sq += __shfl_xor_sync(0xffffffffu, sq, o);
            dp += __shfl_xor_sync(0xffffffffu, dp, o);
        }
        if (lane == 0) {
            float rinv = rsqrtf(fmaxf(sq, 1e-12f));
            float avg  = rinv * dp / fmaxf(nv, 1e-9f);
            float lam  = lambda_so[r * O_ + ctr];
            float w    = fmaxf(lam / fmaxf(nv, 1.0f), 0.0f) * (1.0f - avg);
            out[b * R_ + r] = w;
        }
    }
}

// ---------------------------------------------------------------------------
// Launch contract
// Inputs (metadata order): 0 l_local [B,R,D] f32, 1 h_context [B,N,D] f32,
// 2 lambda_so [R,O] f32, 3 center_o [B] i32, 4 o_types [B,N] i32,
// 5 adj_mask [B,N] bool, 6 two_hop_mask [B,N] bool.  Output [B,R] f32.
// ---------------------------------------------------------------------------
extern "C" void kernel_launch(void* const* d_in, const int* in_sizes, int n_in,
                              void* d_out, int out_size) {
    const float* l_local   = (const float*)d_in[0];
    const float* h_context = (const float*)d_in[1];
    const float* lambda_so = (const float*)d_in[2];
    const int*   center_o  = (const int*)d_in[3];
    const int*   o_types   = (const int*)d_in[4];
    const void*  adj_mask  = d_in[5];
    const void*  two_mask  = d_in[6];
    float*       out       = (float*)d_out;

    ssfw_fused<<<dim3(B_, SPLIT_), THREADS_>>>(l_local, h_context, lambda_so,
                                               center_o, o_types,
                                               adj_mask, two_mask, out);
}